// round 12
// baseline (speedup 1.0000x reference)
#include <cuda_runtime.h>
#include <cuda_bf16.h>
#include <math.h>
#include <cstdint>

#define NB 32
#define NT 1024
#define NE 256
#define NH 4
#define NHD 64
#define NP 32
#define NM (NB*NT)

#define SPSZ ((size_t)NB*NH*NT*32)   // words per q/k/v split plane

// ---- scratch (static device globals; no runtime allocation) ----
__device__ float g_ao [(size_t)NM*NE];
__device__ float g_bs [NM];
__device__ int   g_pid[NM];
// packed bf16x2 hi/lo planes
__device__ uint32_t g_xhi [(size_t)NM*16],  g_xlo [(size_t)NM*16];     // x [32768][16w]
__device__ uint32_t g_hhi [(size_t)NM*128], g_hlo [(size_t)NM*128];    // h [32768][128w]
__device__ uint32_t g_sphi[3*SPSZ],         g_splo[3*SPSZ];            // q|k|v [b][h][t][32w]
__device__ uint32_t g_chi [(size_t)NM*128], g_clo [(size_t)NM*128];    // ctx [32768][128w]
__device__ uint32_t g_pehi[(size_t)NB*NP*128], g_pelo[(size_t)NB*NP*128];
// weights packed
__device__ uint32_t g_wip_hi[256*16],  g_wip_lo[256*16];
__device__ uint32_t g_win_hi[768*128], g_win_lo[768*128];
__device__ uint32_t g_wo_hi [256*128], g_wo_lo [256*128];
__device__ uint32_t g_wpr_hi[256*128], g_wpr_lo[256*128];

// ============================================================================
// helpers
// ============================================================================
__device__ __forceinline__ uint32_t cvta_s(const void* p) {
    return (uint32_t)__cvta_generic_to_shared(p);
}
__device__ __forceinline__ void split_pack_bf16(float x0, float x1,
                                                uint32_t& hi, uint32_t& lo) {
    uint32_t h;
    asm("cvt.rn.bf16x2.f32 %0, %1, %2;" : "=r"(h) : "f"(x1), "f"(x0));
    float h0 = __uint_as_float(h << 16);
    float h1 = __uint_as_float(h & 0xffff0000u);
    float l0 = x0 - h0;
    float l1 = x1 - h1;
    uint32_t l;
    asm("cvt.rn.bf16x2.f32 %0, %1, %2;" : "=r"(l) : "f"(l1), "f"(l0));
    hi = h; lo = l;
}
__device__ __forceinline__ void mma_bf16(float* d, const uint32_t* a, const uint32_t* b) {
    asm volatile(
        "mma.sync.aligned.m16n8k16.row.col.f32.bf16.bf16.f32 "
        "{%0,%1,%2,%3}, {%4,%5,%6,%7}, {%8,%9}, {%0,%1,%2,%3};"
        : "+f"(d[0]), "+f"(d[1]), "+f"(d[2]), "+f"(d[3])
        : "r"(a[0]), "r"(a[1]), "r"(a[2]), "r"(a[3]), "r"(b[0]), "r"(b[1]));
}
__device__ __forceinline__ void ldsm_x4(uint32_t* r, uint32_t a) {
    asm volatile("ldmatrix.sync.aligned.m8n8.x4.shared.b16 {%0,%1,%2,%3}, [%4];"
        : "=r"(r[0]), "=r"(r[1]), "=r"(r[2]), "=r"(r[3]) : "r"(a));
}
__device__ __forceinline__ void ldsm_x4_t(uint32_t* r, uint32_t a) {
    asm volatile("ldmatrix.sync.aligned.m8n8.x4.trans.shared.b16 {%0,%1,%2,%3}, [%4];"
        : "=r"(r[0]), "=r"(r[1]), "=r"(r[2]), "=r"(r[3]) : "r"(a));
}

// ============================================================================
// Split fp32 row-major matrix into packed bf16x2 hi/lo planes (8 floats/thr).
// ============================================================================
__global__ __launch_bounds__(256) void split_kernel(
    const float* __restrict__ src, uint32_t* __restrict__ hi,
    uint32_t* __restrict__ lo, int n8)
{
    const int i = blockIdx.x*256 + threadIdx.x;
    if (i >= n8) return;
    float4 a = ((const float4*)src)[2*i];
    float4 b = ((const float4*)src)[2*i + 1];
    uint32_t hw[4], lw[4];
    split_pack_bf16(a.x, a.y, hw[0], lw[0]);
    split_pack_bf16(a.z, a.w, hw[1], lw[1]);
    split_pack_bf16(b.x, b.y, hw[2], lw[2]);
    split_pack_bf16(b.z, b.w, hw[3], lw[3]);
    ((uint4*)hi)[i] = make_uint4(hw[0], hw[1], hw[2], hw[3]);
    ((uint4*)lo)[i] = make_uint4(lw[0], lw[1], lw[2], lw[3]);
}

// ============================================================================
// GEMM: C[M,N] = A[M,K] @ W[N,K]^T + bias, bf16x3, packed inputs, ldmatrix.
// mode 0: fp32 C out.  mode 1: packed row-major Ohi/Olo out.
// mode 2: packed qkv-layout out ([arr][b][h][t][32w]; q scaled by 0.125).
// ============================================================================
__global__ __launch_bounds__(256) void gemm_mma_kernel(
    const uint32_t* __restrict__ Ahi, const uint32_t* __restrict__ Alo,
    const uint32_t* __restrict__ Whi, const uint32_t* __restrict__ Wlo,
    const float* __restrict__ bias, float* __restrict__ C,
    uint32_t* __restrict__ Ohi, uint32_t* __restrict__ Olo,
    int Ndim, int Kdim, int mode)
{
    __shared__ uint32_t sAhi[128*12], sAlo[128*12];
    __shared__ uint32_t sBhi[128*12], sBlo[128*12];

    const int tid  = threadIdx.x;
    const int wid  = tid >> 5;
    const int lane = tid & 31;
    const int g    = lane >> 2;
    const int tig  = lane & 3;
    const int wm   = wid >> 2;
    const int wn   = wid & 3;
    const int bm   = blockIdx.y << 7;
    const int bn   = blockIdx.x << 7;

    float c[4][4][4];
#pragma unroll
    for (int mi = 0; mi < 4; mi++)
#pragma unroll
        for (int nj = 0; nj < 4; nj++)
#pragma unroll
            for (int r = 0; r < 4; r++) c[mi][nj][r] = 0.f;

    const int row  = tid >> 1;
    const int half = tid & 1;
    const int Kw   = Kdim >> 1;
    const uint32_t* Aph = Ahi + (size_t)(bm + row)*Kw + half*4;
    const uint32_t* Apl = Alo + (size_t)(bm + row)*Kw + half*4;
    const uint32_t* Wph = Whi + (size_t)(bn + row)*Kw + half*4;
    const uint32_t* Wpl = Wlo + (size_t)(bn + row)*Kw + half*4;
    const int so = row*12 + half*4;

    const uint32_t sAhiB = cvta_s(sAhi), sAloB = cvta_s(sAlo);
    const uint32_t sBhiB = cvta_s(sBhi), sBloB = cvta_s(sBlo);
    const int t8  = lane & 7;
    const int sel = lane >> 3;
    const uint32_t afrag = (uint32_t)((((lane & 15) + wm*64)*12 + (lane >> 4)*4) * 4);
    const uint32_t bfrag = (uint32_t)(((wn*32 + (sel >> 1)*8 + t8)*12 + (sel & 1)*4) * 4);

    const int nch = Kdim >> 4;
    for (int ch = 0; ch < nch; ch++) {
        __syncthreads();
        {
            const int gw = ch*8;
            *(uint4*)&sAhi[so] = *(const uint4*)(Aph + gw);
            *(uint4*)&sAlo[so] = *(const uint4*)(Apl + gw);
            *(uint4*)&sBhi[so] = *(const uint4*)(Wph + gw);
            *(uint4*)&sBlo[so] = *(const uint4*)(Wpl + gw);
        }
        __syncthreads();

        uint32_t ahi[4][4], alo[4][4];
#pragma unroll
        for (int mi = 0; mi < 4; mi++) {
            ldsm_x4(ahi[mi], sAhiB + afrag + mi*768);
            ldsm_x4(alo[mi], sAloB + afrag + mi*768);
        }
        uint32_t bhi[8], blo[8];
        ldsm_x4(bhi + 0, sBhiB + bfrag);
        ldsm_x4(bhi + 4, sBhiB + bfrag + 768);
        ldsm_x4(blo + 0, sBloB + bfrag);
        ldsm_x4(blo + 4, sBloB + bfrag + 768);

#pragma unroll
        for (int mi = 0; mi < 4; mi++)
#pragma unroll
            for (int nj = 0; nj < 4; nj++)
                mma_bf16(c[mi][nj], ahi[mi], bhi + 2*nj);
#pragma unroll
        for (int mi = 0; mi < 4; mi++)
#pragma unroll
            for (int nj = 0; nj < 4; nj++)
                mma_bf16(c[mi][nj], ahi[mi], blo + 2*nj);
#pragma unroll
        for (int mi = 0; mi < 4; mi++)
#pragma unroll
            for (int nj = 0; nj < 4; nj++)
                mma_bf16(c[mi][nj], alo[mi], bhi + 2*nj);
    }

#pragma unroll
    for (int mi = 0; mi < 4; mi++) {
#pragma unroll
        for (int nj = 0; nj < 4; nj++) {
            const int cc = bn + wn*32 + nj*8 + 2*tig;
            const int r0 = bm + wm*64 + mi*16 + g;
            float2 bb = *(const float2*)(bias + cc);
            float v00 = c[mi][nj][0] + bb.x, v01 = c[mi][nj][1] + bb.y;
            float v10 = c[mi][nj][2] + bb.x, v11 = c[mi][nj][3] + bb.y;
            if (mode == 0) {
                *(float2*)(C + (size_t)r0 * Ndim + cc)       = make_float2(v00, v01);
                *(float2*)(C + (size_t)(r0 + 8) * Ndim + cc) = make_float2(v10, v11);
            } else if (mode == 1) {
                uint32_t h0, l0, h1, l1;
                split_pack_bf16(v00, v01, h0, l0);
                split_pack_bf16(v10, v11, h1, l1);
                const size_t i0 = (size_t)r0*(Ndim >> 1) + (cc >> 1);
                Ohi[i0] = h0; Olo[i0] = l0;
                Ohi[i0 + (Ndim >> 1)*8] = h1; Olo[i0 + (Ndim >> 1)*8] = l1;
            } else {
                const int arr = cc >> 8;
                const int rem = cc & 255;
                const int hh  = rem >> 6;
                const int word = (rem & 63) >> 1;
                const float sc = (arr == 0) ? 0.125f : 1.f;
                uint32_t h0, l0, h1, l1;
                split_pack_bf16(v00*sc, v01*sc, h0, l0);
                split_pack_bf16(v10*sc, v11*sc, h1, l1);
                const int bb2 = r0 >> 10, t0 = r0 & 1023;
                const size_t i0 = (((size_t)arr*128 + bb2*4 + hh)*1024 + t0)*32 + word;
                Ohi[i0] = h0; Olo[i0] = l0;
                Ohi[i0 + 256] = h1; Olo[i0 + 256] = l1;   // row +8 -> +8*32 words
            }
        }
    }
}

// ============================================================================
// Flash attention, bf16x3 + ldmatrix, BQ=128 (8 warps). All inputs packed.
// Epilogue writes packed ctx (row-major [32768][128w]).
// ============================================================================
__global__ __launch_bounds__(256) void flash_mma_kernel(
    const uint32_t* __restrict__ qhi_g, const uint32_t* __restrict__ qlo_g,
    const uint32_t* __restrict__ khi, const uint32_t* __restrict__ klo,
    const uint32_t* __restrict__ vhi, const uint32_t* __restrict__ vlo,
    uint32_t* __restrict__ chi, uint32_t* __restrict__ clo)
{
    __shared__ uint32_t sKhi[32*36], sKlo[32*36];
    __shared__ uint32_t sVhi[32*36], sVlo[32*36];
    __shared__ uint32_t sPhi[128*20], sPlo[128*20];

    const int tid  = threadIdx.x;
    const int w    = tid >> 5;
    const int lane = tid & 31;
    const int g    = lane >> 2;
    const int tig  = lane & 3;

    const int qb = blockIdx.x;
    const int bh = blockIdx.y;
    const int b  = bh >> 2, h = bh & 3;
    const int qstart = qb << 7;

    // ---- persistent Q fragments (already scaled+split by qkv epilogue) ----
    uint32_t qhi[4][4], qlo[4][4];
    {
        const uint32_t* qh = qhi_g + ((size_t)(b*4 + h)*1024 + qstart + 16*w + g)*32;
        const uint32_t* ql = qlo_g + ((size_t)(b*4 + h)*1024 + qstart + 16*w + g)*32;
#pragma unroll
        for (int kf = 0; kf < 4; kf++) {
            qhi[kf][0] = qh[8*kf + tig];
            qhi[kf][1] = qh[256 + 8*kf + tig];
            qhi[kf][2] = qh[8*kf + tig + 4];
            qhi[kf][3] = qh[256 + 8*kf + tig + 4];
            qlo[kf][0] = ql[8*kf + tig];
            qlo[kf][1] = ql[256 + 8*kf + tig];
            qlo[kf][2] = ql[8*kf + tig + 4];
            qlo[kf][3] = ql[256 + 8*kf + tig + 4];
        }
    }

    float o[8][4];
#pragma unroll
    for (int j = 0; j < 8; j++)
#pragma unroll
        for (int r = 0; r < 4; r++) o[j][r] = 0.f;
    float l0 = 0.f, l1 = 0.f;

    const int fr = tid >> 3;
    const int fc = (tid & 7) * 4;
    const size_t gbase = (size_t)((b*4 + h)*1024) * 32;

    const int t8  = lane & 7;
    const int sel = lane >> 3;
    const uint32_t sKhiB = cvta_s(sKhi), sKloB = cvta_s(sKlo);
    const uint32_t sVhiB = cvta_s(sVhi), sVloB = cvta_s(sVlo);
    const uint32_t sPhiB = cvta_s(sPhi), sPloB = cvta_s(sPlo);
    const uint32_t kfrag = (uint32_t)((((sel >> 1)*8 + t8)*36 + (sel & 1)*4) * 4);
    const uint32_t pfrag = (uint32_t)(((16*w + (sel & 1)*8 + t8)*20 + (sel >> 1)*4) * 4);
    const uint32_t vfrag = (uint32_t)((((sel & 1)*8 + t8)*36 + (sel >> 1)*4) * 4);

    for (int kb = 0; kb < 32; kb++) {
        __syncthreads();
        {
            const size_t go = gbase + (size_t)(kb*32 + fr)*32 + fc;
            const int so = fr*36 + fc;
            *(uint4*)&sKhi[so] = *(const uint4*)&khi[go];
            *(uint4*)&sKlo[so] = *(const uint4*)&klo[go];
            *(uint4*)&sVhi[so] = *(const uint4*)&vhi[go];
            *(uint4*)&sVlo[so] = *(const uint4*)&vlo[go];
        }
        __syncthreads();

        float s_hi[4][4], s_er[4][4];
#pragma unroll
        for (int j = 0; j < 4; j++)
#pragma unroll
            for (int r = 0; r < 4; r++) { s_hi[j][r] = 0.f; s_er[j][r] = 0.f; }
#pragma unroll
        for (int kf = 0; kf < 4; kf++) {
            uint32_t bh8[8], bl8[8];
            ldsm_x4(bh8 + 0, sKhiB + kfrag + kf*32);
            ldsm_x4(bh8 + 4, sKhiB + kfrag + 2304 + kf*32);
            ldsm_x4(bl8 + 0, sKloB + kfrag + kf*32);
            ldsm_x4(bl8 + 4, sKloB + kfrag + 2304 + kf*32);
#pragma unroll
            for (int j = 0; j < 4; j++) mma_bf16(s_hi[j], qhi[kf], bh8 + 2*j);
#pragma unroll
            for (int j = 0; j < 4; j++) mma_bf16(s_er[j], qhi[kf], bl8 + 2*j);
#pragma unroll
            for (int j = 0; j < 4; j++) mma_bf16(s_er[j], qlo[kf], bh8 + 2*j);
        }

        float p[4][4];
        float sum0 = 0.f, sum1 = 0.f;
#pragma unroll
        for (int j = 0; j < 4; j++) {
            p[j][0] = __expf(s_hi[j][0] + s_er[j][0]);
            p[j][1] = __expf(s_hi[j][1] + s_er[j][1]);
            p[j][2] = __expf(s_hi[j][2] + s_er[j][2]);
            p[j][3] = __expf(s_hi[j][3] + s_er[j][3]);
            sum0 += p[j][0] + p[j][1];
            sum1 += p[j][2] + p[j][3];
        }
        sum0 += __shfl_xor_sync(0xffffffffu, sum0, 1);
        sum0 += __shfl_xor_sync(0xffffffffu, sum0, 2);
        sum1 += __shfl_xor_sync(0xffffffffu, sum1, 1);
        sum1 += __shfl_xor_sync(0xffffffffu, sum1, 2);
        l0 += sum0;
        l1 += sum1;

        {
            const int pr0 = (16*w + g    )*20;
            const int pr1 = (16*w + g + 8)*20;
#pragma unroll
            for (int j = 0; j < 4; j++) {
                split_pack_bf16(p[j][0], p[j][1], sPhi[pr0 + 4*j + tig], sPlo[pr0 + 4*j + tig]);
                split_pack_bf16(p[j][2], p[j][3], sPhi[pr1 + 4*j + tig], sPlo[pr1 + 4*j + tig]);
            }
        }
        __syncwarp();

#pragma unroll
        for (int kf = 0; kf < 2; kf++) {
            uint32_t ph[4], pl[4];
            ldsm_x4(ph, sPhiB + pfrag + kf*32);
            ldsm_x4(pl, sPloB + pfrag + kf*32);
#pragma unroll
            for (int j0 = 0; j0 < 8; j0 += 2) {
                uint32_t vh4[4], vl4[4];
                ldsm_x4_t(vh4, sVhiB + vfrag + kf*2304 + j0*16);
                ldsm_x4_t(vl4, sVloB + vfrag + kf*2304 + j0*16);
                mma_bf16(o[j0],   ph, vh4 + 0);
                mma_bf16(o[j0+1], ph, vh4 + 2);
                mma_bf16(o[j0],   ph, vl4 + 0);
                mma_bf16(o[j0+1], ph, vl4 + 2);
                mma_bf16(o[j0],   pl, vh4 + 0);
                mma_bf16(o[j0+1], pl, vh4 + 2);
            }
        }
    }

    // ---- finalize: divide by l, split, write packed ctx ----
    const float inv0 = 1.f / l0, inv1 = 1.f / l1;
    const size_t r0 = (size_t)(b*NT) + qstart + 16*w + g;
    uint32_t* c0h = chi + r0*128 + h*32 + tig;
    uint32_t* c0l = clo + r0*128 + h*32 + tig;
#pragma unroll
    for (int j = 0; j < 8; j++) {
        uint32_t h0, l0w, h1, l1w;
        split_pack_bf16(o[j][0]*inv0, o[j][1]*inv0, h0, l0w);
        split_pack_bf16(o[j][2]*inv1, o[j][3]*inv1, h1, l1w);
        c0h[4*j] = h0;        c0l[4*j] = l0w;
        c0h[8*128 + 4*j] = h1; c0l[8*128 + 4*j] = l1w;
    }
}

// ============================================================================
// Boundary MLP (reads fp32 ao): one warp per row, lane = hidden unit.
// ============================================================================
__global__ __launch_bounds__(256) void boundary_kernel(
    const float* __restrict__ ao, const float* __restrict__ w1,
    const float* __restrict__ b1, const float* __restrict__ w2,
    const float* __restrict__ b2, float* __restrict__ bscore)
{
    int row  = (blockIdx.x << 3) + (threadIdx.x >> 5);
    int lane = threadIdx.x & 31;
    const float4* a = (const float4*)(ao + (size_t)row * NE);
    const float4* w = (const float4*)(w1 + lane * NE);
    float acc = 0.f;
#pragma unroll 16
    for (int d = 0; d < 64; d++) {
        float4 av = a[d], wv = w[d];
        acc += av.x*wv.x + av.y*wv.y + av.z*wv.z + av.w*wv.w;
    }
    float hh = fmaxf(acc + b1[lane], 0.f);
    float s = hh * w2[lane];
#pragma unroll
    for (int off = 16; off; off >>= 1)
        s += __shfl_xor_sync(0xffffffffu, s, off);
    if (lane == 0)
        bscore[row] = 1.f / (1.f + expf(-(s + b2[0])));
}

// ============================================================================
// Per-batch inclusive cumsum (double) -> normalized -> patch ids.
// ============================================================================
__global__ __launch_bounds__(1024) void scan_kernel(
    const float* __restrict__ bscore, int* __restrict__ pid)
{
    __shared__ double sa[1024], sb[1024];
    int b = blockIdx.x, t = threadIdx.x;
    sa[t] = (double)bscore[b*NT + t];
    __syncthreads();
    double* src = sa; double* dst = sb;
#pragma unroll
    for (int off = 1; off < 1024; off <<= 1) {
        double v = src[t];
        if (t >= off) v += src[t - off];
        dst[t] = v;
        __syncthreads();
        double* tmp = src; src = dst; dst = tmp;
    }
    double total = src[1023] + 1e-6;
    double cbp = src[t] / total;
    int p = (int)floor(cbp * (double)NP);
    if (p > NP-1) p = NP-1;
    if (p < 0) p = 0;
    pid[b*NT + t] = p;
}

__device__ __forceinline__ int lower_bound_dev(const int* a, int n, int key) {
    int lo = 0, hi = n;
    while (lo < hi) { int mid = (lo + hi) >> 1; if (a[mid] < key) lo = mid + 1; else hi = mid; }
    return lo;
}

// ============================================================================
// Segment-mean pooling; writes PACKED pe for the patch projection GEMM.
// ============================================================================
__global__ __launch_bounds__(256) void pool_kernel(
    const float* __restrict__ ao, const int* __restrict__ pid,
    uint32_t* __restrict__ pehi, uint32_t* __restrict__ pelo)
{
    __shared__ float sc[256];
    int bp = blockIdx.x;
    int b = bp >> 5, p = bp & 31;
    const int* pa = pid + b*NT;
    int s = lower_bound_dev(pa, NT, p);
    int e = lower_bound_dev(pa, NT, p+1);
    float inv = 1.f / (float)((e - s) > 0 ? (e - s) : 1);
    int col = threadIdx.x;
    float sum = 0.f;
    for (int t = s; t < e; t++)
        sum += ao[((size_t)(b*NT) + t) * NE + col];
    sc[col] = sum * inv;
    __syncthreads();
    if (col < 128) {
        uint32_t hw, lw;
        split_pack_bf16(sc[2*col], sc[2*col + 1], hw, lw);
        pehi[(size_t)bp*128 + col] = hw;
        pelo[(size_t)bp*128 + col] = lw;
    }
}

// ============================================================================
extern "C" void kernel_launch(void* const* d_in, const int* in_sizes, int n_in,
                              void* d_out, int out_size)
{
    (void)in_sizes; (void)n_in; (void)out_size;
    const float* x        = (const float*)d_in[0];
    const float* ip_w     = (const float*)d_in[1];
    const float* ip_b     = (const float*)d_in[2];
    const float* inproj_w = (const float*)d_in[3];
    const float* inproj_b = (const float*)d_in[4];
    const float* out_w    = (const float*)d_in[5];
    const float* out_b    = (const float*)d_in[6];
    const float* bp_w1    = (const float*)d_in[7];
    const float* bp_b1    = (const float*)d_in[8];
    const float* bp_w2    = (const float*)d_in[9];
    const float* bp_b2    = (const float*)d_in[10];
    const float* pr_w     = (const float*)d_in[11];
    const float* pr_b     = (const float*)d_in[12];
    float* out = (float*)d_out;

    void* p;
    float *ao, *bs; int* pid;
    uint32_t *xhi,*xlo,*hhi,*hlo,*sphi,*splo,*chi,*clo,*pehi,*pelo;
    uint32_t *wip_hi,*wip_lo,*win_hi,*win_lo,*wo_hi,*wo_lo,*wpr_hi,*wpr_lo;
    cudaGetSymbolAddress(&p, g_ao);   ao   = (float*)p;
    cudaGetSymbolAddress(&p, g_bs);   bs   = (float*)p;
    cudaGetSymbolAddress(&p, g_pid);  pid  = (int*)p;
    cudaGetSymbolAddress(&p, g_xhi);  xhi  = (uint32_t*)p;
    cudaGetSymbolAddress(&p, g_xlo);  xlo  = (uint32_t*)p;
    cudaGetSymbolAddress(&p, g_hhi);  hhi  = (uint32_t*)p;
    cudaGetSymbolAddress(&p, g_hlo);  hlo  = (uint32_t*)p;
    cudaGetSymbolAddress(&p, g_sphi); sphi = (uint32_t*)p;
    cudaGetSymbolAddress(&p, g_splo); splo = (uint32_t*)p;
    cudaGetSymbolAddress(&p, g_chi);  chi  = (uint32_t*)p;
    cudaGetSymbolAddress(&p, g_clo);  clo  = (uint32_t*)p;
    cudaGetSymbolAddress(&p, g_pehi); pehi = (uint32_t*)p;
    cudaGetSymbolAddress(&p, g_pelo); pelo = (uint32_t*)p;
    cudaGetSymbolAddress(&p, g_wip_hi); wip_hi = (uint32_t*)p;
    cudaGetSymbolAddress(&p, g_wip_lo); wip_lo = (uint32_t*)p;
    cudaGetSymbolAddress(&p, g_win_hi); win_hi = (uint32_t*)p;
    cudaGetSymbolAddress(&p, g_win_lo); win_lo = (uint32_t*)p;
    cudaGetSymbolAddress(&p, g_wo_hi);  wo_hi  = (uint32_t*)p;
    cudaGetSymbolAddress(&p, g_wo_lo);  wo_lo  = (uint32_t*)p;
    cudaGetSymbolAddress(&p, g_wpr_hi); wpr_hi = (uint32_t*)p;
    cudaGetSymbolAddress(&p, g_wpr_lo); wpr_lo = (uint32_t*)p;

    dim3 blk(256);
    // 0) split graph inputs into packed bf16 hi/lo
    split_kernel<<<(NM*32/8 + 255)/256, blk>>>(x, xhi, xlo, NM*32/8);
    split_kernel<<<(256*32/8 + 255)/256, blk>>>(ip_w, wip_hi, wip_lo, 256*32/8);
    split_kernel<<<(768*256/8 + 255)/256, blk>>>(inproj_w, win_hi, win_lo, 768*256/8);
    split_kernel<<<(256*256/8 + 255)/256, blk>>>(out_w, wo_hi, wo_lo, 256*256/8);
    split_kernel<<<(256*256/8 + 255)/256, blk>>>(pr_w, wpr_hi, wpr_lo, 256*256/8);
    // 1) input projection -> packed h
    gemm_mma_kernel<<<dim3(NE/128, NM/128), blk>>>(xhi, xlo, wip_hi, wip_lo, ip_b,
        nullptr, hhi, hlo, NE, 32, 1);
    // 2) qkv projection -> packed q|k|v planes (q pre-scaled by 0.125)
    gemm_mma_kernel<<<dim3(3*NE/128, NM/128), blk>>>(hhi, hlo, win_hi, win_lo, inproj_b,
        nullptr, sphi, splo, 3*NE, NE, 2);
    // 3) attention -> packed ctx
    flash_mma_kernel<<<dim3(NT/128, NB*NH), blk>>>(
        sphi, splo, sphi + SPSZ, splo + SPSZ, sphi + 2*SPSZ, splo + 2*SPSZ, chi, clo);
    // 4) out projection -> fp32 ao
    gemm_mma_kernel<<<dim3(NE/128, NM/128), blk>>>(chi, clo, wo_hi, wo_lo, out_b,
        ao, nullptr, nullptr, NE, NE, 0);
    // 5) boundary scores
    boundary_kernel<<<NM/8, blk>>>(ao, bp_w1, bp_b1, bp_w2, bp_b2, bs);
    // 6) cumsum + patch ids
    scan_kernel<<<NB, NT>>>(bs, pid);
    // 7) segment-mean pooling -> packed pe
    pool_kernel<<<NB*NP, NE>>>(ao, pid, pehi, pelo);
    // 8) patch projection -> output [32,32,256]
    gemm_mma_kernel<<<dim3(NE/128, (NB*NP)/128), blk>>>(pehi, pelo, wpr_hi, wpr_lo, pr_b,
        out, nullptr, nullptr, NE, NE, 0);
}

// round 13
// speedup vs baseline: 1.2558x; 1.2558x over previous
#include <cuda_runtime.h>
#include <cuda_bf16.h>
#include <math.h>
#include <cstdint>

#define NB 32
#define NT 1024
#define NE 256
#define NH 4
#define NHD 64
#define NP 32
#define NM (NB*NT)

// ---- scratch (static device globals; no runtime allocation) ----
__device__ float g_qkv[(size_t)NM*3*NE];
__device__ float g_ctx[(size_t)NM*NE];
__device__ float g_ao [(size_t)NM*NE];
__device__ float g_bs [NM];
__device__ int   g_pid[NM];
__device__ float g_pe [NB*NP*NE];
__device__ float g_wc [768*32];     // folded weight  Win @ Wip
__device__ float g_bc [768];        // folded bias    Win @ b_ip + b_in
// pre-split K/V, packed bf16x2 words, layout [b][h][t][32 words]
__device__ uint32_t g_khi[(size_t)NB*NH*NT*32];
__device__ uint32_t g_klo[(size_t)NB*NH*NT*32];
__device__ uint32_t g_vhi[(size_t)NB*NH*NT*32];
__device__ uint32_t g_vlo[(size_t)NB*NH*NT*32];

// ============================================================================
// helpers
// ============================================================================
__device__ __forceinline__ uint32_t cvta_s(const void* p) {
    return (uint32_t)__cvta_generic_to_shared(p);
}
__device__ __forceinline__ void split_pack_bf16(float x0, float x1,
                                                uint32_t& hi, uint32_t& lo) {
    uint32_t h;
    asm("cvt.rn.bf16x2.f32 %0, %1, %2;" : "=r"(h) : "f"(x1), "f"(x0));
    float h0 = __uint_as_float(h << 16);
    float h1 = __uint_as_float(h & 0xffff0000u);
    float l0 = x0 - h0;
    float l1 = x1 - h1;
    uint32_t l;
    asm("cvt.rn.bf16x2.f32 %0, %1, %2;" : "=r"(l) : "f"(l1), "f"(l0));
    hi = h; lo = l;
}
__device__ __forceinline__ void mma_bf16(float* d, const uint32_t* a, const uint32_t* b) {
    asm volatile(
        "mma.sync.aligned.m16n8k16.row.col.f32.bf16.bf16.f32 "
        "{%0,%1,%2,%3}, {%4,%5,%6,%7}, {%8,%9}, {%0,%1,%2,%3};"
        : "+f"(d[0]), "+f"(d[1]), "+f"(d[2]), "+f"(d[3])
        : "r"(a[0]), "r"(a[1]), "r"(a[2]), "r"(a[3]), "r"(b[0]), "r"(b[1]));
}
__device__ __forceinline__ void ldsm_x4(uint32_t* r, uint32_t a) {
    asm volatile("ldmatrix.sync.aligned.m8n8.x4.shared.b16 {%0,%1,%2,%3}, [%4];"
        : "=r"(r[0]), "=r"(r[1]), "=r"(r[2]), "=r"(r[3]) : "r"(a));
}
__device__ __forceinline__ void ldsm_x4_t(uint32_t* r, uint32_t a) {
    asm volatile("ldmatrix.sync.aligned.m8n8.x4.trans.shared.b16 {%0,%1,%2,%3}, [%4];"
        : "=r"(r[0]), "=r"(r[1]), "=r"(r[2]), "=r"(r[3]) : "r"(a));
}

// ============================================================================
// Fold input projection into qkv: Wc = Win @ Wip  [768,32],
// bc = Win @ b_ip + b_in  [768].  fp32, grid 768 x 32 threads.
// ============================================================================
__global__ __launch_bounds__(32) void fold_kernel(
    const float* __restrict__ win, const float* __restrict__ ipw,
    const float* __restrict__ ipb, const float* __restrict__ inb,
    float* __restrict__ wc, float* __restrict__ bc)
{
    const int i = blockIdx.x;
    const int j = threadIdx.x;
    const float* wr = win + i*256;
    float acc = 0.f;
#pragma unroll 8
    for (int k = 0; k < 256; k++)
        acc += wr[k] * ipw[k*32 + j];
    wc[i*32 + j] = acc;
    float bacc = 0.f;
    for (int k = j; k < 256; k += 32)
        bacc += wr[k] * ipb[k];
#pragma unroll
    for (int off = 16; off; off >>= 1)
        bacc += __shfl_xor_sync(0xffffffffu, bacc, off);
    if (j == 0) bc[i] = bacc + inb[i];
}

// ============================================================================
// Pre-split K and V into packed bf16x2 hi/lo word arrays, [b][h][t][32w].
// ============================================================================
__global__ __launch_bounds__(256) void presplit_kernel(
    const float* __restrict__ qkv,
    uint32_t* __restrict__ khi, uint32_t* __restrict__ klo,
    uint32_t* __restrict__ vhi, uint32_t* __restrict__ vlo)
{
    const int n = blockIdx.x * 256 + threadIdx.x;
    const int r = n >> 5, inner = n & 31;
    const int kv = inner >> 4, h = (inner >> 2) & 3, dc = inner & 3;
    const float* src = qkv + (size_t)r*768 + 256 + kv*256 + h*64 + dc*16;
    const int b = r >> 10, t = r & 1023;
    uint32_t* dh = kv ? vhi : khi;
    uint32_t* dl = kv ? vlo : klo;
    const size_t off = ((size_t)((b*4 + h)*1024 + t))*32 + dc*8;
    uint32_t hw[8], lw[8];
#pragma unroll
    for (int i = 0; i < 4; i++) {
        float4 v = *(const float4*)(src + 4*i);
        split_pack_bf16(v.x, v.y, hw[2*i],   lw[2*i]);
        split_pack_bf16(v.z, v.w, hw[2*i+1], lw[2*i+1]);
    }
    *(uint4*)&dh[off]     = make_uint4(hw[0], hw[1], hw[2], hw[3]);
    *(uint4*)&dh[off + 4] = make_uint4(hw[4], hw[5], hw[6], hw[7]);
    *(uint4*)&dl[off]     = make_uint4(lw[0], lw[1], lw[2], lw[3]);
    *(uint4*)&dl[off + 4] = make_uint4(lw[4], lw[5], lw[6], lw[7]);
}

// ============================================================================
// C[M,N] = A[M,K] @ W[N,K]^T + bias, bf16x3 GEMM + ldmatrix (R11 version).
// ============================================================================
__global__ __launch_bounds__(256) void gemm_mma_kernel(
    const float* __restrict__ A, const float* __restrict__ W,
    const float* __restrict__ bias, float* __restrict__ C,
    int Ndim, int Kdim)
{
    __shared__ uint32_t sAhi[128*12], sAlo[128*12];
    __shared__ uint32_t sBhi[128*12], sBlo[128*12];

    const int tid  = threadIdx.x;
    const int wid  = tid >> 5;
    const int lane = tid & 31;
    const int g    = lane >> 2;
    const int tig  = lane & 3;
    const int wm   = wid >> 2;
    const int wn   = wid & 3;
    const int bm   = blockIdx.y << 7;
    const int bn   = blockIdx.x << 7;

    float c[4][4][4];
#pragma unroll
    for (int mi = 0; mi < 4; mi++)
#pragma unroll
        for (int nj = 0; nj < 4; nj++)
#pragma unroll
            for (int r = 0; r < 4; r++) c[mi][nj][r] = 0.f;

    const int row  = tid >> 1;
    const int half = tid & 1;
    const float* Ap = A + (size_t)(bm + row) * Kdim + half*8;
    const float* Wp = W + (size_t)(bn + row) * Kdim + half*8;
    const int sbase = row*12 + half*4;

    const uint32_t sAhiB = cvta_s(sAhi), sAloB = cvta_s(sAlo);
    const uint32_t sBhiB = cvta_s(sBhi), sBloB = cvta_s(sBlo);
    const int t8  = lane & 7;
    const int sel = lane >> 3;
    const uint32_t afrag = (uint32_t)((((lane & 15) + wm*64)*12 + (lane >> 4)*4) * 4);
    const uint32_t bfrag = (uint32_t)(((wn*32 + (sel >> 1)*8 + t8)*12 + (sel & 1)*4) * 4);

    const int nch = Kdim >> 4;
    for (int ch = 0; ch < nch; ch++) {
        const int k0 = ch << 4;
        __syncthreads();
        {
            float4 a0 = *(const float4*)(Ap + k0);
            float4 a1 = *(const float4*)(Ap + k0 + 4);
            float4 b0 = *(const float4*)(Wp + k0);
            float4 b1 = *(const float4*)(Wp + k0 + 4);
            split_pack_bf16(a0.x, a0.y, sAhi[sbase+0], sAlo[sbase+0]);
            split_pack_bf16(a0.z, a0.w, sAhi[sbase+1], sAlo[sbase+1]);
            split_pack_bf16(a1.x, a1.y, sAhi[sbase+2], sAlo[sbase+2]);
            split_pack_bf16(a1.z, a1.w, sAhi[sbase+3], sAlo[sbase+3]);
            split_pack_bf16(b0.x, b0.y, sBhi[sbase+0], sBlo[sbase+0]);
            split_pack_bf16(b0.z, b0.w, sBhi[sbase+1], sBlo[sbase+1]);
            split_pack_bf16(b1.x, b1.y, sBhi[sbase+2], sBlo[sbase+2]);
            split_pack_bf16(b1.z, b1.w, sBhi[sbase+3], sBlo[sbase+3]);
        }
        __syncthreads();

        uint32_t ahi[4][4], alo[4][4];
#pragma unroll
        for (int mi = 0; mi < 4; mi++) {
            ldsm_x4(ahi[mi], sAhiB + afrag + mi*768);
            ldsm_x4(alo[mi], sAloB + afrag + mi*768);
        }
        uint32_t bhi[8], blo[8];
        ldsm_x4(bhi + 0, sBhiB + bfrag);
        ldsm_x4(bhi + 4, sBhiB + bfrag + 768);
        ldsm_x4(blo + 0, sBloB + bfrag);
        ldsm_x4(blo + 4, sBloB + bfrag + 768);

#pragma unroll
        for (int mi = 0; mi < 4; mi++)
#pragma unroll
            for (int nj = 0; nj < 4; nj++)
                mma_bf16(c[mi][nj], ahi[mi], bhi + 2*nj);
#pragma unroll
        for (int mi = 0; mi < 4; mi++)
#pragma unroll
            for (int nj = 0; nj < 4; nj++)
                mma_bf16(c[mi][nj], ahi[mi], blo + 2*nj);
#pragma unroll
        for (int mi = 0; mi < 4; mi++)
#pragma unroll
            for (int nj = 0; nj < 4; nj++)
                mma_bf16(c[mi][nj], alo[mi], bhi + 2*nj);
    }

#pragma unroll
    for (int mi = 0; mi < 4; mi++) {
#pragma unroll
        for (int nj = 0; nj < 4; nj++) {
            const int cc = bn + wn*32 + nj*8 + 2*tig;
            const int r0 = bm + wm*64 + mi*16 + g;
            float2 bb = *(const float2*)(bias + cc);
            *(float2*)(C + (size_t)r0 * Ndim + cc) =
                make_float2(c[mi][nj][0] + bb.x, c[mi][nj][1] + bb.y);
            *(float2*)(C + (size_t)(r0 + 8) * Ndim + cc) =
                make_float2(c[mi][nj][2] + bb.x, c[mi][nj][3] + bb.y);
        }
    }
}

// ============================================================================
// Flash attention, bf16x3 m16n8k16 + ldmatrix. BQ=128 (8 warps, 256 thr).
// ============================================================================
__global__ __launch_bounds__(256) void flash_mma_kernel(
    const float* __restrict__ qkv,
    const uint32_t* __restrict__ khi, const uint32_t* __restrict__ klo,
    const uint32_t* __restrict__ vhi, const uint32_t* __restrict__ vlo,
    float* __restrict__ ctx)
{
    __shared__ uint32_t sKhi[32*36], sKlo[32*36];
    __shared__ uint32_t sVhi[32*36], sVlo[32*36];
    __shared__ uint32_t sPhi[128*20], sPlo[128*20];

    const int tid  = threadIdx.x;
    const int w    = tid >> 5;
    const int lane = tid & 31;
    const int g    = lane >> 2;
    const int tig  = lane & 3;

    const int qb = blockIdx.x;
    const int bh = blockIdx.y;
    const int b  = bh >> 2, h = bh & 3;

    const float* base = qkv + (size_t)b * NT * (3*NE);
    const int qoff = h * NHD;
    const int qstart = qb << 7;

    uint32_t qhi[4][4], qlo[4][4];
    {
        const float* r0p = base + (size_t)(qstart + 16*w + g) * (3*NE) + qoff;
        const float* r1p = base + (size_t)(qstart + 16*w + g + 8) * (3*NE) + qoff;
#pragma unroll
        for (int kf = 0; kf < 4; kf++) {
            float2 v00 = *(const float2*)(r0p + 16*kf + 2*tig);
            float2 v10 = *(const float2*)(r1p + 16*kf + 2*tig);
            float2 v01 = *(const float2*)(r0p + 16*kf + 2*tig + 8);
            float2 v11 = *(const float2*)(r1p + 16*kf + 2*tig + 8);
            split_pack_bf16(v00.x*0.125f, v00.y*0.125f, qhi[kf][0], qlo[kf][0]);
            split_pack_bf16(v10.x*0.125f, v10.y*0.125f, qhi[kf][1], qlo[kf][1]);
            split_pack_bf16(v01.x*0.125f, v01.y*0.125f, qhi[kf][2], qlo[kf][2]);
            split_pack_bf16(v11.x*0.125f, v11.y*0.125f, qhi[kf][3], qlo[kf][3]);
        }
    }

    float o[8][4];
#pragma unroll
    for (int j = 0; j < 8; j++)
#pragma unroll
        for (int r = 0; r < 4; r++) o[j][r] = 0.f;
    float l0 = 0.f, l1 = 0.f;

    const int fr = tid >> 3;
    const int fc = (tid & 7) * 4;
    const size_t gbase = (size_t)((b*4 + h)*1024) * 32;

    const int t8  = lane & 7;
    const int sel = lane >> 3;
    const uint32_t sKhiB = cvta_s(sKhi), sKloB = cvta_s(sKlo);
    const uint32_t sVhiB = cvta_s(sVhi), sVloB = cvta_s(sVlo);
    const uint32_t sPhiB = cvta_s(sPhi), sPloB = cvta_s(sPlo);
    const uint32_t kfrag = (uint32_t)((((sel >> 1)*8 + t8)*36 + (sel & 1)*4) * 4);
    const uint32_t pfrag = (uint32_t)(((16*w + (sel & 1)*8 + t8)*20 + (sel >> 1)*4) * 4);
    const uint32_t vfrag = (uint32_t)((((sel & 1)*8 + t8)*36 + (sel >> 1)*4) * 4);

    for (int kb = 0; kb < 32; kb++) {
        __syncthreads();
        {
            const size_t go = gbase + (size_t)(kb*32 + fr)*32 + fc;
            const int so = fr*36 + fc;
            *(uint4*)&sKhi[so] = *(const uint4*)&khi[go];
            *(uint4*)&sKlo[so] = *(const uint4*)&klo[go];
            *(uint4*)&sVhi[so] = *(const uint4*)&vhi[go];
            *(uint4*)&sVlo[so] = *(const uint4*)&vlo[go];
        }
        __syncthreads();

        float s_hi[4][4], s_er[4][4];
#pragma unroll
        for (int j = 0; j < 4; j++)
#pragma unroll
            for (int r = 0; r < 4; r++) { s_hi[j][r] = 0.f; s_er[j][r] = 0.f; }
#pragma unroll
        for (int kf = 0; kf < 4; kf++) {
            uint32_t bh8[8], bl8[8];
            ldsm_x4(bh8 + 0, sKhiB + kfrag + kf*32);
            ldsm_x4(bh8 + 4, sKhiB + kfrag + 2304 + kf*32);
            ldsm_x4(bl8 + 0, sKloB + kfrag + kf*32);
            ldsm_x4(bl8 + 4, sKloB + kfrag + 2304 + kf*32);
#pragma unroll
            for (int j = 0; j < 4; j++) mma_bf16(s_hi[j], qhi[kf], bh8 + 2*j);
#pragma unroll
            for (int j = 0; j < 4; j++) mma_bf16(s_er[j], qhi[kf], bl8 + 2*j);
#pragma unroll
            for (int j = 0; j < 4; j++) mma_bf16(s_er[j], qlo[kf], bh8 + 2*j);
        }

        float p[4][4];
        float sum0 = 0.f, sum1 = 0.f;
#pragma unroll
        for (int j = 0; j < 4; j++) {
            p[j][0] = __expf(s_hi[j][0] + s_er[j][0]);
            p[j][1] = __expf(s_hi[j][1] + s_er[j][1]);
            p[j][2] = __expf(s_hi[j][2] + s_er[j][2]);
            p[j][3] = __expf(s_hi[j][3] + s_er[j][3]);
            sum0 += p[j][0] + p[j][1];
            sum1 += p[j][2] + p[j][3];
        }
        sum0 += __shfl_xor_sync(0xffffffffu, sum0, 1);
        sum0 += __shfl_xor_sync(0xffffffffu, sum0, 2);
        sum1 += __shfl_xor_sync(0xffffffffu, sum1, 1);
        sum1 += __shfl_xor_sync(0xffffffffu, sum1, 2);
        l0 += sum0;
        l1 += sum1;

        {
            const int pr0 = (16*w + g    )*20;
            const int pr1 = (16*w + g + 8)*20;
#pragma unroll
            for (int j = 0; j < 4; j++) {
                split_pack_bf16(p[j][0], p[j][1], sPhi[pr0 + 4*j + tig], sPlo[pr0 + 4*j + tig]);
                split_pack_bf16(p[j][2], p[j][3], sPhi[pr1 + 4*j + tig], sPlo[pr1 + 4*j + tig]);
            }
        }
        __syncwarp();

#pragma unroll
        for (int kf = 0; kf < 2; kf++) {
            uint32_t ph[4], pl[4];
            ldsm_x4(ph, sPhiB + pfrag + kf*32);
            ldsm_x4(pl, sPloB + pfrag + kf*32);
#pragma unroll
            for (int j0 = 0; j0 < 8; j0 += 2) {
                uint32_t vh4[4], vl4[4];
                ldsm_x4_t(vh4, sVhiB + vfrag + kf*2304 + j0*16);
                ldsm_x4_t(vl4, sVloB + vfrag + kf*2304 + j0*16);
                mma_bf16(o[j0],   ph, vh4 + 0);
                mma_bf16(o[j0+1], ph, vh4 + 2);
                mma_bf16(o[j0],   ph, vl4 + 0);
                mma_bf16(o[j0+1], ph, vl4 + 2);
                mma_bf16(o[j0],   pl, vh4 + 0);
                mma_bf16(o[j0+1], pl, vh4 + 2);
            }
        }
    }

    const float inv0 = 1.f / l0, inv1 = 1.f / l1;
    float* c0 = ctx + ((size_t)(b*NT) + qstart + 16*w + g    ) * NE + h*NHD;
    float* c1 = ctx + ((size_t)(b*NT) + qstart + 16*w + g + 8) * NE + h*NHD;
#pragma unroll
    for (int j = 0; j < 8; j++) {
        *(float2*)(c0 + 8*j + 2*tig) = make_float2(o[j][0]*inv0, o[j][1]*inv0);
        *(float2*)(c1 + 8*j + 2*tig) = make_float2(o[j][2]*inv1, o[j][3]*inv1);
    }
}

// ============================================================================
// Boundary MLP: one warp per row, lane = hidden unit.
// ============================================================================
__global__ __launch_bounds__(256) void boundary_kernel(
    const float* __restrict__ ao, const float* __restrict__ w1,
    const float* __restrict__ b1, const float* __restrict__ w2,
    const float* __restrict__ b2, float* __restrict__ bscore)
{
    int row  = (blockIdx.x << 3) + (threadIdx.x >> 5);
    int lane = threadIdx.x & 31;
    const float4* a = (const float4*)(ao + (size_t)row * NE);
    const float4* w = (const float4*)(w1 + lane * NE);
    float acc = 0.f;
#pragma unroll 16
    for (int d = 0; d < 64; d++) {
        float4 av = a[d], wv = w[d];
        acc += av.x*wv.x + av.y*wv.y + av.z*wv.z + av.w*wv.w;
    }
    float hh = fmaxf(acc + b1[lane], 0.f);
    float s = hh * w2[lane];
#pragma unroll
    for (int off = 16; off; off >>= 1)
        s += __shfl_xor_sync(0xffffffffu, s, off);
    if (lane == 0)
        bscore[row] = 1.f / (1.f + expf(-(s + b2[0])));
}

// ============================================================================
// Per-batch inclusive cumsum (double) -> normalized -> patch ids.
// ============================================================================
__global__ __launch_bounds__(1024) void scan_kernel(
    const float* __restrict__ bscore, int* __restrict__ pid)
{
    __shared__ double sa[1024], sb[1024];
    int b = blockIdx.x, t = threadIdx.x;
    sa[t] = (double)bscore[b*NT + t];
    __syncthreads();
    double* src = sa; double* dst = sb;
#pragma unroll
    for (int off = 1; off < 1024; off <<= 1) {
        double v = src[t];
        if (t >= off) v += src[t - off];
        dst[t] = v;
        __syncthreads();
        double* tmp = src; src = dst; dst = tmp;
    }
    double total = src[1023] + 1e-6;
    double cbp = src[t] / total;
    int p = (int)floor(cbp * (double)NP);
    if (p > NP-1) p = NP-1;
    if (p < 0) p = 0;
    pid[b*NT + t] = p;
}

__device__ __forceinline__ int lower_bound_dev(const int* a, int n, int key) {
    int lo = 0, hi = n;
    while (lo < hi) { int mid = (lo + hi) >> 1; if (a[mid] < key) lo = mid + 1; else hi = mid; }
    return lo;
}

// ============================================================================
// Segment-mean pooling; pid monotone -> contiguous ranges, no atomics.
// ============================================================================
__global__ __launch_bounds__(256) void pool_kernel(
    const float* __restrict__ ao, const int* __restrict__ pid,
    float* __restrict__ pe)
{
    int bp = blockIdx.x;
    int b = bp >> 5, p = bp & 31;
    const int* pa = pid + b*NT;
    int s = lower_bound_dev(pa, NT, p);
    int e = lower_bound_dev(pa, NT, p+1);
    float inv = 1.f / (float)((e - s) > 0 ? (e - s) : 1);
    int col = threadIdx.x;
    float sum = 0.f;
    for (int t = s; t < e; t++)
        sum += ao[((size_t)(b*NT) + t) * NE + col];
    pe[(size_t)bp * NE + col] = sum * inv;
}

// ============================================================================
extern "C" void kernel_launch(void* const* d_in, const int* in_sizes, int n_in,
                              void* d_out, int out_size)
{
    (void)in_sizes; (void)n_in; (void)out_size;
    const float* x        = (const float*)d_in[0];
    const float* ip_w     = (const float*)d_in[1];
    const float* ip_b     = (const float*)d_in[2];
    const float* inproj_w = (const float*)d_in[3];
    const float* inproj_b = (const float*)d_in[4];
    const float* out_w    = (const float*)d_in[5];
    const float* out_b    = (const float*)d_in[6];
    const float* bp_w1    = (const float*)d_in[7];
    const float* bp_b1    = (const float*)d_in[8];
    const float* bp_w2    = (const float*)d_in[9];
    const float* bp_b2    = (const float*)d_in[10];
    const float* pr_w     = (const float*)d_in[11];
    const float* pr_b     = (const float*)d_in[12];
    float* out = (float*)d_out;

    void* p;
    float *qkv, *ctx, *ao, *bs, *pe, *wc, *bc; int* pid;
    uint32_t *khi, *klo, *vhi, *vlo;
    cudaGetSymbolAddress(&p, g_qkv); qkv = (float*)p;
    cudaGetSymbolAddress(&p, g_ctx); ctx = (float*)p;
    cudaGetSymbolAddress(&p, g_ao);  ao  = (float*)p;
    cudaGetSymbolAddress(&p, g_bs);  bs  = (float*)p;
    cudaGetSymbolAddress(&p, g_pid); pid = (int*)p;
    cudaGetSymbolAddress(&p, g_pe);  pe  = (float*)p;
    cudaGetSymbolAddress(&p, g_wc);  wc  = (float*)p;
    cudaGetSymbolAddress(&p, g_bc);  bc  = (float*)p;
    cudaGetSymbolAddress(&p, g_khi); khi = (uint32_t*)p;
    cudaGetSymbolAddress(&p, g_klo); klo = (uint32_t*)p;
    cudaGetSymbolAddress(&p, g_vhi); vhi = (uint32_t*)p;
    cudaGetSymbolAddress(&p, g_vlo); vlo = (uint32_t*)p;

    dim3 blk(256);
    // 0) fold ip into qkv: Wc = Win@Wip, bc = Win@b_ip + b_in  (fp32)
    fold_kernel<<<768, 32>>>(inproj_w, ip_w, ip_b, inproj_b, wc, bc);
    // 1) fused qkv projection: [32768,32] @ Wc^T -> [32768,768]  (K=32)
    gemm_mma_kernel<<<dim3(3*NE/128, NM/128), blk>>>(x, wc, bc, qkv, 3*NE, 32);
    // 2) pre-split K/V to bf16 hi/lo
    presplit_kernel<<<4096, blk>>>(qkv, khi, klo, vhi, vlo);
    // 3) attention -> ctx  (BQ=128)
    flash_mma_kernel<<<dim3(NT/128, NB*NH), blk>>>(qkv, khi, klo, vhi, vlo, ctx);
    // 4) out projection
    gemm_mma_kernel<<<dim3(NE/128, NM/128), blk>>>(ctx, out_w, out_b, ao, NE, NE);
    // 5) boundary scores
    boundary_kernel<<<NM/8, blk>>>(ao, bp_w1, bp_b1, bp_w2, bp_b2, bs);
    // 6) cumsum + patch ids
    scan_kernel<<<NB, NT>>>(bs, pid);
    // 7) segment-mean pooling
    pool_kernel<<<NB*NP, NE>>>(ao, pid, pe);
    // 8) patch projection -> output [32,32,256]
    gemm_mma_kernel<<<dim3(NE/128, (NB*NP)/128), blk>>>(pe, pr_w, pr_b, out, NE, NE);
}

// round 15
// speedup vs baseline: 1.2966x; 1.0324x over previous
#include <cuda_runtime.h>
#include <cuda_bf16.h>
#include <math.h>
#include <cstdint>

#define NB 32
#define NT 1024
#define NE 256
#define NH 4
#define NHD 64
#define NP 32
#define NM (NB*NT)

// ---- scratch (static device globals; no runtime allocation) ----
__device__ float g_qkv[(size_t)NM*3*NE];
__device__ float g_ctx[(size_t)NM*NE];
__device__ float g_ao [(size_t)NM*NE];
__device__ float g_bs [NM];
__device__ int   g_pid[NM];
__device__ float g_pe [NB*NP*NE];
__device__ float g_wc [768*32];     // folded weight  Win @ Wip
__device__ float g_bc [768];        // folded bias    Win @ b_ip + b_in
// pre-split K/V, packed bf16x2 words, layout [b][h][t][32 words]
__device__ uint32_t g_khi[(size_t)NB*NH*NT*32];
__device__ uint32_t g_klo[(size_t)NB*NH*NT*32];
__device__ uint32_t g_vhi[(size_t)NB*NH*NT*32];
__device__ uint32_t g_vlo[(size_t)NB*NH*NT*32];

// ============================================================================
// helpers
// ============================================================================
__device__ __forceinline__ uint32_t cvta_s(const void* p) {
    return (uint32_t)__cvta_generic_to_shared(p);
}
__device__ __forceinline__ void split_pack_bf16(float x0, float x1,
                                                uint32_t& hi, uint32_t& lo) {
    uint32_t h;
    asm("cvt.rn.bf16x2.f32 %0, %1, %2;" : "=r"(h) : "f"(x1), "f"(x0));
    float h0 = __uint_as_float(h << 16);
    float h1 = __uint_as_float(h & 0xffff0000u);
    float l0 = x0 - h0;
    float l1 = x1 - h1;
    uint32_t l;
    asm("cvt.rn.bf16x2.f32 %0, %1, %2;" : "=r"(l) : "f"(l1), "f"(l0));
    hi = h; lo = l;
}
__device__ __forceinline__ void mma_bf16(float* d, const uint32_t* a, const uint32_t* b) {
    asm volatile(
        "mma.sync.aligned.m16n8k16.row.col.f32.bf16.bf16.f32 "
        "{%0,%1,%2,%3}, {%4,%5,%6,%7}, {%8,%9}, {%0,%1,%2,%3};"
        : "+f"(d[0]), "+f"(d[1]), "+f"(d[2]), "+f"(d[3])
        : "r"(a[0]), "r"(a[1]), "r"(a[2]), "r"(a[3]), "r"(b[0]), "r"(b[1]));
}
__device__ __forceinline__ void ldsm_x4(uint32_t* r, uint32_t a) {
    asm volatile("ldmatrix.sync.aligned.m8n8.x4.shared.b16 {%0,%1,%2,%3}, [%4];"
        : "=r"(r[0]), "=r"(r[1]), "=r"(r[2]), "=r"(r[3]) : "r"(a));
}
__device__ __forceinline__ void ldsm_x4_t(uint32_t* r, uint32_t a) {
    asm volatile("ldmatrix.sync.aligned.m8n8.x4.trans.shared.b16 {%0,%1,%2,%3}, [%4];"
        : "=r"(r[0]), "=r"(r[1]), "=r"(r[2]), "=r"(r[3]) : "r"(a));
}

// ============================================================================
// Fold input projection into qkv: Wc = Win @ Wip  [768,32],
// bc = Win @ b_ip + b_in  [768].  fp32.
// ============================================================================
__global__ __launch_bounds__(32) void fold_kernel(
    const float* __restrict__ win, const float* __restrict__ ipw,
    const float* __restrict__ ipb, const float* __restrict__ inb,
    float* __restrict__ wc, float* __restrict__ bc)
{
    const int i = blockIdx.x;
    const int j = threadIdx.x;
    const float* wr = win + i*256;
    float acc = 0.f;
#pragma unroll 8
    for (int k = 0; k < 256; k++)
        acc += wr[k] * ipw[k*32 + j];
    wc[i*32 + j] = acc;
    float bacc = 0.f;
    for (int k = j; k < 256; k += 32)
        bacc += wr[k] * ipb[k];
#pragma unroll
    for (int off = 16; off; off >>= 1)
        bacc += __shfl_xor_sync(0xffffffffu, bacc, off);
    if (j == 0) bc[i] = bacc + inb[i];
}

// ============================================================================
// Pre-split K and V into packed bf16x2 hi/lo word arrays, [b][h][t][32w].
// ============================================================================
__global__ __launch_bounds__(256) void presplit_kernel(
    const float* __restrict__ qkv,
    uint32_t* __restrict__ khi, uint32_t* __restrict__ klo,
    uint32_t* __restrict__ vhi, uint32_t* __restrict__ vlo)
{
    const int n = blockIdx.x * 256 + threadIdx.x;
    const int r = n >> 5, inner = n & 31;
    const int kv = inner >> 4, h = (inner >> 2) & 3, dc = inner & 3;
    const float* src = qkv + (size_t)r*768 + 256 + kv*256 + h*64 + dc*16;
    const int b = r >> 10, t = r & 1023;
    uint32_t* dh = kv ? vhi : khi;
    uint32_t* dl = kv ? vlo : klo;
    const size_t off = ((size_t)((b*4 + h)*1024 + t))*32 + dc*8;
    uint32_t hw[8], lw[8];
#pragma unroll
    for (int i = 0; i < 4; i++) {
        float4 v = *(const float4*)(src + 4*i);
        split_pack_bf16(v.x, v.y, hw[2*i],   lw[2*i]);
        split_pack_bf16(v.z, v.w, hw[2*i+1], lw[2*i+1]);
    }
    *(uint4*)&dh[off]     = make_uint4(hw[0], hw[1], hw[2], hw[3]);
    *(uint4*)&dh[off + 4] = make_uint4(hw[4], hw[5], hw[6], hw[7]);
    *(uint4*)&dl[off]     = make_uint4(lw[0], lw[1], lw[2], lw[3]);
    *(uint4*)&dl[off + 4] = make_uint4(lw[4], lw[5], lw[6], lw[7]);
}

// ============================================================================
// C[M,N] = A[M,K] @ W[N,K]^T + bias, bf16x3 GEMM + ldmatrix (R11 version).
// ============================================================================
__global__ __launch_bounds__(256) void gemm_mma_kernel(
    const float* __restrict__ A, const float* __restrict__ W,
    const float* __restrict__ bias, float* __restrict__ C,
    int Ndim, int Kdim)
{
    __shared__ uint32_t sAhi[128*12], sAlo[128*12];
    __shared__ uint32_t sBhi[128*12], sBlo[128*12];

    const int tid  = threadIdx.x;
    const int wid  = tid >> 5;
    const int lane = tid & 31;
    const int g    = lane >> 2;
    const int tig  = lane & 3;
    const int wm   = wid >> 2;
    const int wn   = wid & 3;
    const int bm   = blockIdx.y << 7;
    const int bn   = blockIdx.x << 7;

    float c[4][4][4];
#pragma unroll
    for (int mi = 0; mi < 4; mi++)
#pragma unroll
        for (int nj = 0; nj < 4; nj++)
#pragma unroll
            for (int r = 0; r < 4; r++) c[mi][nj][r] = 0.f;

    const int row  = tid >> 1;
    const int half = tid & 1;
    const float* Ap = A + (size_t)(bm + row) * Kdim + half*8;
    const float* Wp = W + (size_t)(bn + row) * Kdim + half*8;
    const int sbase = row*12 + half*4;

    const uint32_t sAhiB = cvta_s(sAhi), sAloB = cvta_s(sAlo);
    const uint32_t sBhiB = cvta_s(sBhi), sBloB = cvta_s(sBlo);
    const int t8  = lane & 7;
    const int sel = lane >> 3;
    const uint32_t afrag = (uint32_t)((((lane & 15) + wm*64)*12 + (lane >> 4)*4) * 4);
    const uint32_t bfrag = (uint32_t)(((wn*32 + (sel >> 1)*8 + t8)*12 + (sel & 1)*4) * 4);

    const int nch = Kdim >> 4;
    for (int ch = 0; ch < nch; ch++) {
        const int k0 = ch << 4;
        __syncthreads();
        {
            float4 a0 = *(const float4*)(Ap + k0);
            float4 a1 = *(const float4*)(Ap + k0 + 4);
            float4 b0 = *(const float4*)(Wp + k0);
            float4 b1 = *(const float4*)(Wp + k0 + 4);
            split_pack_bf16(a0.x, a0.y, sAhi[sbase+0], sAlo[sbase+0]);
            split_pack_bf16(a0.z, a0.w, sAhi[sbase+1], sAlo[sbase+1]);
            split_pack_bf16(a1.x, a1.y, sAhi[sbase+2], sAlo[sbase+2]);
            split_pack_bf16(a1.z, a1.w, sAhi[sbase+3], sAlo[sbase+3]);
            split_pack_bf16(b0.x, b0.y, sBhi[sbase+0], sBlo[sbase+0]);
            split_pack_bf16(b0.z, b0.w, sBhi[sbase+1], sBlo[sbase+1]);
            split_pack_bf16(b1.x, b1.y, sBhi[sbase+2], sBlo[sbase+2]);
            split_pack_bf16(b1.z, b1.w, sBhi[sbase+3], sBlo[sbase+3]);
        }
        __syncthreads();

        uint32_t ahi[4][4], alo[4][4];
#pragma unroll
        for (int mi = 0; mi < 4; mi++) {
            ldsm_x4(ahi[mi], sAhiB + afrag + mi*768);
            ldsm_x4(alo[mi], sAloB + afrag + mi*768);
        }
        uint32_t bhi[8], blo[8];
        ldsm_x4(bhi + 0, sBhiB + bfrag);
        ldsm_x4(bhi + 4, sBhiB + bfrag + 768);
        ldsm_x4(blo + 0, sBloB + bfrag);
        ldsm_x4(blo + 4, sBloB + bfrag + 768);

#pragma unroll
        for (int mi = 0; mi < 4; mi++)
#pragma unroll
            for (int nj = 0; nj < 4; nj++)
                mma_bf16(c[mi][nj], ahi[mi], bhi + 2*nj);
#pragma unroll
        for (int mi = 0; mi < 4; mi++)
#pragma unroll
            for (int nj = 0; nj < 4; nj++)
                mma_bf16(c[mi][nj], ahi[mi], blo + 2*nj);
#pragma unroll
        for (int mi = 0; mi < 4; mi++)
#pragma unroll
            for (int nj = 0; nj < 4; nj++)
                mma_bf16(c[mi][nj], alo[mi], bhi + 2*nj);
    }

#pragma unroll
    for (int mi = 0; mi < 4; mi++) {
#pragma unroll
        for (int nj = 0; nj < 4; nj++) {
            const int cc = bn + wn*32 + nj*8 + 2*tig;
            const int r0 = bm + wm*64 + mi*16 + g;
            float2 bb = *(const float2*)(bias + cc);
            *(float2*)(C + (size_t)r0 * Ndim + cc) =
                make_float2(c[mi][nj][0] + bb.x, c[mi][nj][1] + bb.y);
            *(float2*)(C + (size_t)(r0 + 8) * Ndim + cc) =
                make_float2(c[mi][nj][2] + bb.x, c[mi][nj][3] + bb.y);
        }
    }
}

// ============================================================================
// Flash attention, bf16x3 m16n8k16 + ldmatrix. BQ=128 (8 warps, 256 thr).
// P converted C-layout -> A-layout ENTIRELY IN REGISTERS (the m16n8k16
// layouts coincide: phi[r] = pack of p[2kf+?][..]), so no P smem round-trip.
// ============================================================================
__global__ __launch_bounds__(256) void flash_mma_kernel(
    const float* __restrict__ qkv,
    const uint32_t* __restrict__ khi, const uint32_t* __restrict__ klo,
    const uint32_t* __restrict__ vhi, const uint32_t* __restrict__ vlo,
    float* __restrict__ ctx)
{
    __shared__ uint32_t sKhi[32*36], sKlo[32*36];
    __shared__ uint32_t sVhi[32*36], sVlo[32*36];

    const int tid  = threadIdx.x;
    const int w    = tid >> 5;
    const int lane = tid & 31;
    const int g    = lane >> 2;
    const int tig  = lane & 3;

    const int qb = blockIdx.x;
    const int bh = blockIdx.y;
    const int b  = bh >> 2, h = bh & 3;

    const float* base = qkv + (size_t)b * NT * (3*NE);
    const int qoff = h * NHD;
    const int qstart = qb << 7;

    uint32_t qhi[4][4], qlo[4][4];
    {
        const float* r0p = base + (size_t)(qstart + 16*w + g) * (3*NE) + qoff;
        const float* r1p = base + (size_t)(qstart + 16*w + g + 8) * (3*NE) + qoff;
#pragma unroll
        for (int kf = 0; kf < 4; kf++) {
            float2 v00 = *(const float2*)(r0p + 16*kf + 2*tig);
            float2 v10 = *(const float2*)(r1p + 16*kf + 2*tig);
            float2 v01 = *(const float2*)(r0p + 16*kf + 2*tig + 8);
            float2 v11 = *(const float2*)(r1p + 16*kf + 2*tig + 8);
            split_pack_bf16(v00.x*0.125f, v00.y*0.125f, qhi[kf][0], qlo[kf][0]);
            split_pack_bf16(v10.x*0.125f, v10.y*0.125f, qhi[kf][1], qlo[kf][1]);
            split_pack_bf16(v01.x*0.125f, v01.y*0.125f, qhi[kf][2], qlo[kf][2]);
            split_pack_bf16(v11.x*0.125f, v11.y*0.125f, qhi[kf][3], qlo[kf][3]);
        }
    }

    float o[8][4];
#pragma unroll
    for (int j = 0; j < 8; j++)
#pragma unroll
        for (int r = 0; r < 4; r++) o[j][r] = 0.f;
    float l0 = 0.f, l1 = 0.f;

    const int fr = tid >> 3;
    const int fc = (tid & 7) * 4;
    const size_t gbase = (size_t)((b*4 + h)*1024) * 32;

    const int t8  = lane & 7;
    const int sel = lane >> 3;
    const uint32_t sKhiB = cvta_s(sKhi), sKloB = cvta_s(sKlo);
    const uint32_t sVhiB = cvta_s(sVhi), sVloB = cvta_s(sVlo);
    const uint32_t kfrag = (uint32_t)((((sel >> 1)*8 + t8)*36 + (sel & 1)*4) * 4);
    const uint32_t vfrag = (uint32_t)((((sel & 1)*8 + t8)*36 + (sel >> 1)*4) * 4);

    for (int kb = 0; kb < 32; kb++) {
        __syncthreads();
        {
            const size_t go = gbase + (size_t)(kb*32 + fr)*32 + fc;
            const int so = fr*36 + fc;
            *(uint4*)&sKhi[so] = *(const uint4*)&khi[go];
            *(uint4*)&sKlo[so] = *(const uint4*)&klo[go];
            *(uint4*)&sVhi[so] = *(const uint4*)&vhi[go];
            *(uint4*)&sVlo[so] = *(const uint4*)&vlo[go];
        }
        __syncthreads();

        // ---- S = Q K^T with split hi/err accumulators ----
        float s_hi[4][4], s_er[4][4];
#pragma unroll
        for (int j = 0; j < 4; j++)
#pragma unroll
            for (int r = 0; r < 4; r++) { s_hi[j][r] = 0.f; s_er[j][r] = 0.f; }
#pragma unroll
        for (int kf = 0; kf < 4; kf++) {
            uint32_t bh8[8], bl8[8];
            ldsm_x4(bh8 + 0, sKhiB + kfrag + kf*32);
            ldsm_x4(bh8 + 4, sKhiB + kfrag + 2304 + kf*32);
            ldsm_x4(bl8 + 0, sKloB + kfrag + kf*32);
            ldsm_x4(bl8 + 4, sKloB + kfrag + 2304 + kf*32);
#pragma unroll
            for (int j = 0; j < 4; j++) mma_bf16(s_hi[j], qhi[kf], bh8 + 2*j);
#pragma unroll
            for (int j = 0; j < 4; j++) mma_bf16(s_er[j], qhi[kf], bl8 + 2*j);
#pragma unroll
            for (int j = 0; j < 4; j++) mma_bf16(s_er[j], qlo[kf], bh8 + 2*j);
        }

        // ---- softmax weights p = exp(s) (no max shift) ----
        float p[4][4];
        float sum0 = 0.f, sum1 = 0.f;
#pragma unroll
        for (int j = 0; j < 4; j++) {
            p[j][0] = __expf(s_hi[j][0] + s_er[j][0]);
            p[j][1] = __expf(s_hi[j][1] + s_er[j][1]);
            p[j][2] = __expf(s_hi[j][2] + s_er[j][2]);
            p[j][3] = __expf(s_hi[j][3] + s_er[j][3]);
            sum0 += p[j][0] + p[j][1];
            sum1 += p[j][2] + p[j][3];
        }
        sum0 += __shfl_xor_sync(0xffffffffu, sum0, 1);
        sum0 += __shfl_xor_sync(0xffffffffu, sum0, 2);
        sum1 += __shfl_xor_sync(0xffffffffu, sum1, 1);
        sum1 += __shfl_xor_sync(0xffffffffu, sum1, 2);
        l0 += sum0;
        l1 += sum1;

        // ---- O += P V : P A-fragments built directly in registers ----
#pragma unroll
        for (int kf = 0; kf < 2; kf++) {
            uint32_t ph[4], pl[4];
            split_pack_bf16(p[2*kf  ][0], p[2*kf  ][1], ph[0], pl[0]);
            split_pack_bf16(p[2*kf  ][2], p[2*kf  ][3], ph[1], pl[1]);
            split_pack_bf16(p[2*kf+1][0], p[2*kf+1][1], ph[2], pl[2]);
            split_pack_bf16(p[2*kf+1][2], p[2*kf+1][3], ph[3], pl[3]);
#pragma unroll
            for (int j0 = 0; j0 < 8; j0 += 2) {
                uint32_t vh4[4], vl4[4];
                ldsm_x4_t(vh4, sVhiB + vfrag + kf*2304 + j0*16);
                ldsm_x4_t(vl4, sVloB + vfrag + kf*2304 + j0*16);
                mma_bf16(o[j0],   ph, vh4 + 0);
                mma_bf16(o[j0+1], ph, vh4 + 2);
                mma_bf16(o[j0],   ph, vl4 + 0);
                mma_bf16(o[j0+1], ph, vl4 + 2);
                mma_bf16(o[j0],   pl, vh4 + 0);
                mma_bf16(o[j0+1], pl, vh4 + 2);
            }
        }
    }

    const float inv0 = 1.f / l0, inv1 = 1.f / l1;
    float* c0 = ctx + ((size_t)(b*NT) + qstart + 16*w + g    ) * NE + h*NHD;
    float* c1 = ctx + ((size_t)(b*NT) + qstart + 16*w + g + 8) * NE + h*NHD;
#pragma unroll
    for (int j = 0; j < 8; j++) {
        *(float2*)(c0 + 8*j + 2*tig) = make_float2(o[j][0]*inv0, o[j][1]*inv0);
        *(float2*)(c1 + 8*j + 2*tig) = make_float2(o[j][2]*inv1, o[j][3]*inv1);
    }
}

// ============================================================================
// Boundary MLP: one warp per row, lane = hidden unit.
// ============================================================================
__global__ __launch_bounds__(256) void boundary_kernel(
    const float* __restrict__ ao, const float* __restrict__ w1,
    const float* __restrict__ b1, const float* __restrict__ w2,
    const float* __restrict__ b2, float* __restrict__ bscore)
{
    int row  = (blockIdx.x << 3) + (threadIdx.x >> 5);
    int lane = threadIdx.x & 31;
    const float4* a = (const float4*)(ao + (size_t)row * NE);
    const float4* w = (const float4*)(w1 + lane * NE);
    float acc = 0.f;
#pragma unroll 16
    for (int d = 0; d < 64; d++) {
        float4 av = a[d], wv = w[d];
        acc += av.x*wv.x + av.y*wv.y + av.z*wv.z + av.w*wv.w;
    }
    float hh = fmaxf(acc + b1[lane], 0.f);
    float s = hh * w2[lane];
#pragma unroll
    for (int off = 16; off; off >>= 1)
        s += __shfl_xor_sync(0xffffffffu, s, off);
    if (lane == 0)
        bscore[row] = 1.f / (1.f + expf(-(s + b2[0])));
}

// ============================================================================
// Per-batch inclusive cumsum (double) -> normalized -> patch ids.
// ============================================================================
__global__ __launch_bounds__(1024) void scan_kernel(
    const float* __restrict__ bscore, int* __restrict__ pid)
{
    __shared__ double sa[1024], sb[1024];
    int b = blockIdx.x, t = threadIdx.x;
    sa[t] = (double)bscore[b*NT + t];
    __syncthreads();
    double* src = sa; double* dst = sb;
#pragma unroll
    for (int off = 1; off < 1024; off <<= 1) {
        double v = src[t];
        if (t >= off) v += src[t - off];
        dst[t] = v;
        __syncthreads();
        double* tmp = src; src = dst; dst = tmp;
    }
    double total = src[1023] + 1e-6;
    double cbp = src[t] / total;
    int p = (int)floor(cbp * (double)NP);
    if (p > NP-1) p = NP-1;
    if (p < 0) p = 0;
    pid[b*NT + t] = p;
}

__device__ __forceinline__ int lower_bound_dev(const int* a, int n, int key) {
    int lo = 0, hi = n;
    while (lo < hi) { int mid = (lo + hi) >> 1; if (a[mid] < key) lo = mid + 1; else hi = mid; }
    return lo;
}

// ============================================================================
// Segment-mean pooling; pid monotone -> contiguous ranges, no atomics.
// ============================================================================
__global__ __launch_bounds__(256) void pool_kernel(
    const float* __restrict__ ao, const int* __restrict__ pid,
    float* __restrict__ pe)
{
    int bp = blockIdx.x;
    int b = bp >> 5, p = bp & 31;
    const int* pa = pid + b*NT;
    int s = lower_bound_dev(pa, NT, p);
    int e = lower_bound_dev(pa, NT, p+1);
    float inv = 1.f / (float)((e - s) > 0 ? (e - s) : 1);
    int col = threadIdx.x;
    float sum = 0.f;
    for (int t = s; t < e; t++)
        sum += ao[((size_t)(b*NT) + t) * NE + col];
    pe[(size_t)bp * NE + col] = sum * inv;
}

// ============================================================================
extern "C" void kernel_launch(void* const* d_in, const int* in_sizes, int n_in,
                              void* d_out, int out_size)
{
    (void)in_sizes; (void)n_in; (void)out_size;
    const float* x        = (const float*)d_in[0];
    const float* ip_w     = (const float*)d_in[1];
    const float* ip_b     = (const float*)d_in[2];
    const float* inproj_w = (const float*)d_in[3];
    const float* inproj_b = (const float*)d_in[4];
    const float* out_w    = (const float*)d_in[5];
    const float* out_b    = (const float*)d_in[6];
    const float* bp_w1    = (const float*)d_in[7];
    const float* bp_b1    = (const float*)d_in[8];
    const float* bp_w2    = (const float*)d_in[9];
    const float* bp_b2    = (const float*)d_in[10];
    const float* pr_w     = (const float*)d_in[11];
    const float* pr_b     = (const float*)d_in[12];
    float* out = (float*)d_out;

    void* p;
    float *qkv, *ctx, *ao, *bs, *pe, *wc, *bc; int* pid;
    uint32_t *khi, *klo, *vhi, *vlo;
    cudaGetSymbolAddress(&p, g_qkv); qkv = (float*)p;
    cudaGetSymbolAddress(&p, g_ctx); ctx = (float*)p;
    cudaGetSymbolAddress(&p, g_ao);  ao  = (float*)p;
    cudaGetSymbolAddress(&p, g_bs);  bs  = (float*)p;
    cudaGetSymbolAddress(&p, g_pid); pid = (int*)p;
    cudaGetSymbolAddress(&p, g_pe);  pe  = (float*)p;
    cudaGetSymbolAddress(&p, g_wc);  wc  = (float*)p;
    cudaGetSymbolAddress(&p, g_bc);  bc  = (float*)p;
    cudaGetSymbolAddress(&p, g_khi); khi = (uint32_t*)p;
    cudaGetSymbolAddress(&p, g_klo); klo = (uint32_t*)p;
    cudaGetSymbolAddress(&p, g_vhi); vhi = (uint32_t*)p;
    cudaGetSymbolAddress(&p, g_vlo); vlo = (uint32_t*)p;

    dim3 blk(256);
    // 0) fold ip into qkv
    fold_kernel<<<768, 32>>>(inproj_w, ip_w, ip_b, inproj_b, wc, bc);
    // 1) fused qkv projection: [32768,32] @ Wc^T -> [32768,768]  (K=32)
    gemm_mma_kernel<<<dim3(3*NE/128, NM/128), blk>>>(x, wc, bc, qkv, 3*NE, 32);
    // 2) pre-split K/V to bf16 hi/lo
    presplit_kernel<<<4096, blk>>>(qkv, khi, klo, vhi, vlo);
    // 3) attention -> ctx  (BQ=128)
    flash_mma_kernel<<<dim3(NT/128, NB*NH), blk>>>(qkv, khi, klo, vhi, vlo, ctx);
    // 4) out projection
    gemm_mma_kernel<<<dim3(NE/128, NM/128), blk>>>(ctx, out_w, out_b, ao, NE, NE);
    // 5) boundary scores
    boundary_kernel<<<NM/8, blk>>>(ao, bp_w1, bp_b1, bp_w2, bp_b2, bs);
    // 6) cumsum + patch ids
    scan_kernel<<<NB, NT>>>(bs, pid);
    // 7) segment-mean pooling
    pool_kernel<<<NB*NP, NE>>>(ao, pid, pe);
    // 8) patch projection -> output [32,32,256]
    gemm_mma_kernel<<<dim3(NE/128, (NB*NP)/128), blk>>>(pe, pr_w, pr_b, out, NE, NE);
}